// round 2
// baseline (speedup 1.0000x reference)
#include <cuda_runtime.h>
#include <cuda_bf16.h>

// Problem constants (fixed by the dataset)
#define NN 100000
#define NE 1600000
#define NG 512
#define INC 3
#define H1C 64
#define H2C 128
#define OUTC 2

// Scratch (allocation-free rule: __device__ globals). 16B alignment required
// for float4 loads and red.global.add.v4.f32.
__device__ __align__(16) float g_deg [NN];
__device__ __align__(16) float g_dinv[NN];
__device__ __align__(16) float g_xw1 [NN * H1C];
__device__ __align__(16) float g_agg1[NN * H1C];
__device__ __align__(16) float g_xw2 [NN * H2C];
__device__ __align__(16) float g_agg2[NN * H2C];
__device__ __align__(16) float g_pool[NG * H2C];
__device__ __align__(16) float g_cnt [NG];

__device__ __forceinline__ void red_add_v4(float* addr, float4 v) {
    asm volatile("red.global.add.v4.f32 [%0], {%1,%2,%3,%4};"
                 :: "l"(addr), "f"(v.x), "f"(v.y), "f"(v.z), "f"(v.w)
                 : "memory");
}

// ---------------------------------------------------------------- zero scratch
__global__ void k_zero() {
    int i = blockIdx.x * blockDim.x + threadIdx.x;
    if (i < NN) g_deg[i] = 0.f;
    if (i < NG * H2C) g_pool[i] = 0.f;
    if (i < NG) g_cnt[i] = 0.f;
}

// ---------------------------------------------------------------- degree count
__global__ void k_deg(const int* __restrict__ dst) {
    int e = blockIdx.x * blockDim.x + threadIdx.x;
    if (e < NE) atomicAdd(&g_deg[dst[e]], 1.0f);
}

__global__ void k_dinv() {
    int i = blockIdx.x * blockDim.x + threadIdx.x;
    if (i < NN) g_dinv[i] = rsqrtf(g_deg[i] + 1.0f);
}

// ------------------------------------------- layer 1 dense: xw1 = x@W1, agg1 init
// thread t -> node i = t/64, feature j = t%64 (coalesced stores)
__global__ void k_l1(const float* __restrict__ x, const float* __restrict__ W1) {
    int t = blockIdx.x * blockDim.x + threadIdx.x;
    if (t >= NN * H1C) return;
    int i = t >> 6;
    int j = t & 63;
    float x0 = __ldg(&x[i * 3 + 0]);
    float x1 = __ldg(&x[i * 3 + 1]);
    float x2 = __ldg(&x[i * 3 + 2]);
    float v = x0 * __ldg(&W1[j]) + x1 * __ldg(&W1[64 + j]) + x2 * __ldg(&W1[128 + j]);
    g_xw1[t] = v;
    float d = g_dinv[i];
    g_agg1[t] = d * d * v;  // self-loop contribution seeds the accumulator
}

// ------------------------------------------- layer 1 edge scatter (16 lanes/edge)
__global__ void k_e1(const int* __restrict__ src,
                     const int* __restrict__ dst) {
    long long t = (long long)blockIdx.x * blockDim.x + threadIdx.x;
    if (t >= (long long)NE * 16) return;
    int e = (int)(t >> 4);
    int q = ((int)t & 15) * 4;
    int s = src[e];
    int d = dst[e];
    float norm = g_dinv[s] * g_dinv[d];
    float4 v = *(const float4*)&g_xw1[s * H1C + q];
    v.x *= norm; v.y *= norm; v.z *= norm; v.w *= norm;
    red_add_v4(&g_agg1[d * H1C + q], v);
}

// ----------------- layer 2 dense: h1 = relu(agg1+b1); xw2 = h1@W2; agg2 init
// 128 threads/block, each thread owns one W2 column in registers; NPB nodes/block
#define NPB 16
__global__ void __launch_bounds__(128)
k_l2(const float* __restrict__ b1, const float* __restrict__ W2) {
    int tid = threadIdx.x;  // 0..127 = output feature j
    float wcol[64];
#pragma unroll
    for (int k = 0; k < 64; k++) wcol[k] = __ldg(&W2[k * H2C + tid]);

    __shared__ float sh[64];
    int node0 = blockIdx.x * NPB;
    for (int n = 0; n < NPB; n++) {
        int i = node0 + n;
        if (i >= NN) break;
        __syncthreads();
        if (tid < 64) sh[tid] = fmaxf(g_agg1[i * H1C + tid] + __ldg(&b1[tid]), 0.f);
        __syncthreads();
        float sum = 0.f;
#pragma unroll
        for (int k = 0; k < 64; k++) sum = fmaf(sh[k], wcol[k], sum);
        float d = g_dinv[i];
        g_xw2[i * H2C + tid] = sum;
        g_agg2[i * H2C + tid] = d * d * sum;
    }
}

// ------------------------------------------- layer 2 edge scatter (warp/edge)
__global__ void k_e2(const int* __restrict__ src,
                     const int* __restrict__ dst) {
    long long t = (long long)blockIdx.x * blockDim.x + threadIdx.x;
    if (t >= (long long)NE * 32) return;
    int e = (int)(t >> 5);
    int q = ((int)t & 31) * 4;
    int s = src[e];
    int d = dst[e];
    float norm = g_dinv[s] * g_dinv[d];
    float4 v = *(const float4*)&g_xw2[s * H2C + q];
    v.x *= norm; v.y *= norm; v.z *= norm; v.w *= norm;
    red_add_v4(&g_agg2[d * H2C + q], v);
}

// ------------------- pooling: h2 = relu(agg2+b2), scatter-mean into g_pool/g_cnt
__global__ void k_pool(const int* __restrict__ batch,
                       const float* __restrict__ b2) {
    int t = blockIdx.x * blockDim.x + threadIdx.x;
    if (t >= NN * 32) return;
    int i = t >> 5;
    int q = (t & 31) * 4;
    int g = batch[i];
    float4 v = *(const float4*)&g_agg2[i * H2C + q];
    v.x = fmaxf(v.x + __ldg(&b2[q + 0]), 0.f);
    v.y = fmaxf(v.y + __ldg(&b2[q + 1]), 0.f);
    v.z = fmaxf(v.z + __ldg(&b2[q + 2]), 0.f);
    v.w = fmaxf(v.w + __ldg(&b2[q + 3]), 0.f);
    red_add_v4(&g_pool[g * H2C + q], v);
    if (q == 0) atomicAdd(&g_cnt[g], 1.0f);
}

// ------------------------------------------- final: out = (pool/cnt)@Wfc + bfc
__global__ void k_out(const float* __restrict__ Wfc,
                      const float* __restrict__ bfc,
                      float* __restrict__ out) {
    int t = blockIdx.x * blockDim.x + threadIdx.x;
    if (t >= NG * OUTC) return;
    int g = t >> 1;
    int o = t & 1;
    float inv = 1.0f / fmaxf(g_cnt[g], 1.0f);
    float s = 0.f;
#pragma unroll
    for (int k = 0; k < H2C; k++) s = fmaf(g_pool[g * H2C + k], __ldg(&Wfc[k * OUTC + o]), s);
    out[t] = s * inv + __ldg(&bfc[o]);
}

extern "C" void kernel_launch(void* const* d_in, const int* in_sizes, int n_in,
                              void* d_out, int out_size) {
    const float* x   = (const float*)d_in[0];
    const int*   ei  = (const int*)d_in[1];   // [2, E] (int32 in harness)
    const int*   bat = (const int*)d_in[2];   // [N]
    const float* W1  = (const float*)d_in[3];
    const float* b1  = (const float*)d_in[4];
    const float* W2  = (const float*)d_in[5];
    const float* b2  = (const float*)d_in[6];
    const float* Wfc = (const float*)d_in[7];
    const float* bfc = (const float*)d_in[8];
    float*       out = (float*)d_out;

    const int* src = ei;
    const int* dst = ei + NE;

    const int T = 256;
    k_zero<<<(NN + T - 1) / T, T>>>();
    k_deg <<<(NE + T - 1) / T, T>>>(dst);
    k_dinv<<<(NN + T - 1) / T, T>>>();
    k_l1  <<<(NN * H1C + T - 1) / T, T>>>(x, W1);
    k_e1  <<<(int)(((long long)NE * 16 + T - 1) / T), T>>>(src, dst);
    k_l2  <<<(NN + NPB - 1) / NPB, 128>>>(b1, W2);
    k_e2  <<<(int)(((long long)NE * 32 + T - 1) / T), T>>>(src, dst);
    k_pool<<<(NN * 32 + T - 1) / T, T>>>(bat, b2);
    k_out <<<(NG * OUTC + T - 1) / T, T>>>(Wfc, bfc, out);
}

// round 3
// speedup vs baseline: 2.0663x; 2.0663x over previous
#include <cuda_runtime.h>
#include <cuda_bf16.h>

#define NN 100000
#define NE 1600000
#define NG 512
#define H1C 64
#define H2C 128
#define OUTC 2
#define NPB 16

// Scratch (__device__ globals; 16B aligned for float4 + red.v4)
__device__ __align__(16) float g_deg [NN];
__device__ __align__(16) float g_dinv[NN];
__device__ __align__(16) float g_xs  [NN * 3];      // dinv-scaled x
__device__ __align__(16) float g_aggx[NN * 3];      // edge-aggregated xs
__device__ __align__(16) float g_h1s [NN * H1C];    // dinv-scaled relu(layer1)
__device__ __align__(16) float g_aggh[NN * H1C];    // edge-aggregated h1s
__device__ __align__(16) float g_pool[NG * H2C];
__device__ __align__(16) float g_cnt [NG];

__device__ __forceinline__ void red_add_v4(float* addr, float4 v) {
    asm volatile("red.global.add.v4.f32 [%0], {%1,%2,%3,%4};"
                 :: "l"(addr), "f"(v.x), "f"(v.y), "f"(v.z), "f"(v.w)
                 : "memory");
}
__device__ __forceinline__ void red_add_f(float* addr, float v) {
    asm volatile("red.global.add.f32 [%0], %1;" :: "l"(addr), "f"(v) : "memory");
}

// ------------------------------------------------------------------ zero scratch
__global__ void k_zero() {
    int i = blockIdx.x * blockDim.x + threadIdx.x;  // up to NN*64/4 = 1.6M
    float4 z = make_float4(0.f, 0.f, 0.f, 0.f);
    if (i < NN * H1C / 4)  ((float4*)g_aggh)[i] = z;
    if (i < NN * 3 / 4)    ((float4*)g_aggx)[i] = z;
    if (i < NN / 4)        ((float4*)g_deg)[i]  = z;
    if (i < NG * H2C / 4)  ((float4*)g_pool)[i] = z;
    if (i < NG / 4)        ((float4*)g_cnt)[i]  = z;
}

// ------------------------------------------------------------------ degree
__global__ void k_deg(const int* __restrict__ dst) {
    int e = blockIdx.x * blockDim.x + threadIdx.x;
    if (e < NE) red_add_f(&g_deg[dst[e]], 1.0f);
}

// --------------------------------------------- dinv + source-scaled features xs
__global__ void k_dinv(const float* __restrict__ x) {
    int i = blockIdx.x * blockDim.x + threadIdx.x;
    if (i >= NN) return;
    float d = rsqrtf(g_deg[i] + 1.0f);
    g_dinv[i] = d;
    g_xs[i * 3 + 0] = d * x[i * 3 + 0];
    g_xs[i * 3 + 1] = d * x[i * 3 + 1];
    g_xs[i * 3 + 2] = d * x[i * 3 + 2];
}

// -------------------------------------------------- layer-1 edge prop (3 floats)
__global__ void k_ex(const int* __restrict__ src, const int* __restrict__ dst) {
    int e = blockIdx.x * blockDim.x + threadIdx.x;
    if (e >= NE) return;
    int s = src[e], d = dst[e];
    float v0 = g_xs[s * 3 + 0], v1 = g_xs[s * 3 + 1], v2 = g_xs[s * 3 + 2];
    red_add_f(&g_aggx[d * 3 + 0], v0);
    red_add_f(&g_aggx[d * 3 + 1], v1);
    red_add_f(&g_aggx[d * 3 + 2], v2);
}

// ----------- layer-1 dense: h1s = dinv * relu( (dinv*(aggx+xs)) @ W1 + b1 )
__global__ void k_l1(const float* __restrict__ W1, const float* __restrict__ b1) {
    int t = blockIdx.x * blockDim.x + threadIdx.x;
    if (t >= NN * H1C) return;
    int i = t >> 6, f = t & 63;
    float d  = g_dinv[i];
    float a0 = d * (g_aggx[i * 3 + 0] + g_xs[i * 3 + 0]);
    float a1 = d * (g_aggx[i * 3 + 1] + g_xs[i * 3 + 1]);
    float a2 = d * (g_aggx[i * 3 + 2] + g_xs[i * 3 + 2]);
    float v = a0 * __ldg(&W1[f]) + a1 * __ldg(&W1[64 + f]) + a2 * __ldg(&W1[128 + f]);
    g_h1s[t] = d * fmaxf(v + __ldg(&b1[f]), 0.f);
}

// -------------------------------------------- layer-2 edge prop (16 lanes/edge)
__global__ void k_eh(const int* __restrict__ src, const int* __restrict__ dst) {
    long long t = (long long)blockIdx.x * blockDim.x + threadIdx.x;
    if (t >= (long long)NE * 16) return;
    int e = (int)(t >> 4);
    int q = ((int)t & 15) * 4;
    int s = src[e], d = dst[e];
    float4 v = *(const float4*)&g_h1s[s * H1C + q];
    red_add_v4(&g_aggh[d * H1C + q], v);
}

// ---- layer-2 dense + fused mean-pool scatter (batch is sorted -> run-flush)
// agg2[i] = dinv[i]*(aggh[i]+h1s[i]); h2 = relu(agg2@W2 + b2); pool[batch[i]] += h2
__global__ void __launch_bounds__(128)
k_l2(const float* __restrict__ W2, const float* __restrict__ b2,
     const int* __restrict__ batch) {
    int tid = threadIdx.x;  // output feature 0..127
    float wcol[H1C];
#pragma unroll
    for (int k = 0; k < H1C; k++) wcol[k] = __ldg(&W2[k * H2C + tid]);
    float bias = __ldg(&b2[tid]);

    __shared__ float sh[H1C];
    int node0 = blockIdx.x * NPB;
    if (node0 >= NN) return;

    float acc = 0.f;
    float cntacc = 0.f;
    int cur_g = batch[node0];

    for (int n = 0; n < NPB; n++) {
        int i = node0 + n;
        if (i >= NN) break;
        __syncthreads();
        if (tid < H1C) {
            float d = g_dinv[i];
            sh[tid] = d * (g_aggh[i * H1C + tid] + g_h1s[i * H1C + tid]);
        }
        __syncthreads();
        float v = bias;
#pragma unroll
        for (int k = 0; k < H1C; k++) v = fmaf(sh[k], wcol[k], v);
        float h2 = fmaxf(v, 0.f);

        int g = batch[i];
        if (g != cur_g) {
            red_add_f(&g_pool[cur_g * H2C + tid], acc);
            if (tid == 0) red_add_f(&g_cnt[cur_g], cntacc);
            acc = 0.f; cntacc = 0.f; cur_g = g;
        }
        acc += h2;
        cntacc += 1.f;
    }
    red_add_f(&g_pool[cur_g * H2C + tid], acc);
    if (tid == 0) red_add_f(&g_cnt[cur_g], cntacc);
}

// ------------------------------------------------ final: out = (pool/cnt)@Wfc+bfc
__global__ void k_out(const float* __restrict__ Wfc, const float* __restrict__ bfc,
                      float* __restrict__ out) {
    int t = blockIdx.x * blockDim.x + threadIdx.x;
    if (t >= NG * OUTC) return;
    int g = t >> 1, o = t & 1;
    float inv = 1.0f / fmaxf(g_cnt[g], 1.0f);
    float s = 0.f;
#pragma unroll
    for (int k = 0; k < H2C; k++)
        s = fmaf(g_pool[g * H2C + k], __ldg(&Wfc[k * OUTC + o]), s);
    out[t] = s * inv + __ldg(&bfc[o]);
}

extern "C" void kernel_launch(void* const* d_in, const int* in_sizes, int n_in,
                              void* d_out, int out_size) {
    const float* x   = (const float*)d_in[0];
    const int*   ei  = (const int*)d_in[1];   // [2, E] int32
    const int*   bat = (const int*)d_in[2];   // [N] int32
    const float* W1  = (const float*)d_in[3];
    const float* b1  = (const float*)d_in[4];
    const float* W2  = (const float*)d_in[5];
    const float* b2  = (const float*)d_in[6];
    const float* Wfc = (const float*)d_in[7];
    const float* bfc = (const float*)d_in[8];
    float*       out = (float*)d_out;

    const int* src = ei;
    const int* dst = ei + NE;

    const int T = 256;
    k_zero<<<(NN * H1C / 4 + T - 1) / T, T>>>();
    k_deg <<<(NE + T - 1) / T, T>>>(dst);
    k_dinv<<<(NN + T - 1) / T, T>>>(x);
    k_ex  <<<(NE + T - 1) / T, T>>>(src, dst);
    k_l1  <<<(NN * H1C + T - 1) / T, T>>>(W1, b1);
    k_eh  <<<(int)(((long long)NE * 16 + T - 1) / T), T>>>(src, dst);
    k_l2  <<<(NN + NPB - 1) / NPB, 128>>>(W2, b2, bat);
    k_out <<<(NG * OUTC + T - 1) / T, T>>>(Wfc, bfc, out);
}

// round 4
// speedup vs baseline: 2.4509x; 1.1861x over previous
#include <cuda_runtime.h>
#include <cuda_bf16.h>

#define NN 100000
#define NE 1600000
#define NG 512
#define H1C 64
#define H2C 128
#define OUTC 2
#define NPB 32   // nodes per block in k_l2 (2 per iteration)

// Scratch (__device__ globals; 16B aligned for float4 + red.v4)
__device__ __align__(16) float g_deg  [NN];
__device__ __align__(16) float g_dinv [NN];
__device__ __align__(16) float g_xs4  [NN * 4];     // {d*x0, d*x1, d*x2, d}
__device__ __align__(16) float g_aggx4[NN * 4];     // seeded with xs4 (self term)
__device__ __align__(16) float g_h1s  [NN * H1C];   // dinv-scaled relu(layer1)
__device__ __align__(16) float g_aggh [NN * H1C];   // seeded with h1s (self term)
__device__ __align__(16) float g_pool [NG * H2C];
__device__ __align__(16) float g_cnt  [NG];

__device__ __forceinline__ void red_add_v4(float* addr, float4 v) {
    asm volatile("red.global.add.v4.f32 [%0], {%1,%2,%3,%4};"
                 :: "l"(addr), "f"(v.x), "f"(v.y), "f"(v.z), "f"(v.w)
                 : "memory");
}
__device__ __forceinline__ void red_add_f(float* addr, float v) {
    asm volatile("red.global.add.f32 [%0], %1;" :: "l"(addr), "f"(v) : "memory");
}

// ------------------------------------------------ zero: deg, pool, cnt only
__global__ void k_zero() {
    int i = blockIdx.x * blockDim.x + threadIdx.x;
    float4 z = make_float4(0.f, 0.f, 0.f, 0.f);
    if (i < NN / 4)       ((float4*)g_deg)[i]  = z;
    if (i < NG * H2C / 4) ((float4*)g_pool)[i] = z;
    if (i < NG / 4)       ((float4*)g_cnt)[i]  = z;
}

// ------------------------------------------------ degree
__global__ void k_deg(const int* __restrict__ dst) {
    int e = blockIdx.x * blockDim.x + threadIdx.x;
    if (e < NE) red_add_f(&g_deg[dst[e]], 1.0f);
}

// -------------------- dinv + source-scaled xs4; seed aggx4 with self term
__global__ void k_dinv(const float* __restrict__ x) {
    int i = blockIdx.x * blockDim.x + threadIdx.x;
    if (i >= NN) return;
    float d = rsqrtf(g_deg[i] + 1.0f);
    g_dinv[i] = d;
    float4 v = make_float4(d * x[i * 3 + 0], d * x[i * 3 + 1], d * x[i * 3 + 2], d);
    ((float4*)g_xs4)[i]   = v;
    ((float4*)g_aggx4)[i] = v;   // self-loop contribution pre-seeded
}

// ------------------------- layer-1 edge prop: one v4 gather + one v4 red
__global__ void k_ex(const int* __restrict__ src, const int* __restrict__ dst) {
    int e = blockIdx.x * blockDim.x + threadIdx.x;
    if (e >= NE) return;
    int s = src[e], d = dst[e];
    float4 v = ((const float4*)g_xs4)[s];
    red_add_v4(&g_aggx4[d * 4], v);
}

// ------- layer-1 dense: h1s = dinv*relu((dinv*aggx4)@W1 + b1); seed aggh
__global__ void k_l1(const float* __restrict__ W1, const float* __restrict__ b1) {
    int t = blockIdx.x * blockDim.x + threadIdx.x;
    if (t >= NN * H1C) return;
    int i = t >> 6, f = t & 63;
    float d  = g_dinv[i];
    float a0 = d * g_aggx4[i * 4 + 0];
    float a1 = d * g_aggx4[i * 4 + 1];
    float a2 = d * g_aggx4[i * 4 + 2];
    float v = a0 * __ldg(&W1[f]) + a1 * __ldg(&W1[64 + f]) + a2 * __ldg(&W1[128 + f]);
    float h = d * fmaxf(v + __ldg(&b1[f]), 0.f);
    g_h1s[t]  = h;
    g_aggh[t] = h;   // self-loop contribution pre-seeded
}

// ------------------------- layer-2 edge prop (16 lanes/edge, v4 granules)
__global__ void k_eh(const int* __restrict__ src, const int* __restrict__ dst) {
    long long t = (long long)blockIdx.x * blockDim.x + threadIdx.x;
    if (t >= (long long)NE * 16) return;
    int e = (int)(t >> 4);
    int q = ((int)t & 15) * 4;
    int s = src[e], d = dst[e];
    float4 v = *(const float4*)&g_h1s[s * H1C + q];
    red_add_v4(&g_aggh[d * H1C + q], v);
}

// ---- layer-2 dense + fused mean-pool (batch sorted -> run-flush), 2 nodes/iter
__global__ void __launch_bounds__(128)
k_l2(const float* __restrict__ W2, const float* __restrict__ b2,
     const int* __restrict__ batch) {
    int tid = threadIdx.x;           // output feature 0..127
    int half = tid >> 6;             // 0 or 1: which node this thread helps load
    int fl   = tid & 63;
    float wcol[H1C];
#pragma unroll
    for (int k = 0; k < H1C; k++) wcol[k] = __ldg(&W2[k * H2C + tid]);
    float bias = __ldg(&b2[tid]);

    __shared__ float sh[2][H1C];
    int node0 = blockIdx.x * NPB;    // NPB=32, NN=100000 -> 3125 blocks exact
    if (node0 >= NN) return;

    float acc = 0.f, cntacc = 0.f;
    int cur_g = batch[node0];

    for (int n = 0; n < NPB; n += 2) {
        int i0 = node0 + n;
        int il = i0 + half;          // node this thread loads
        __syncthreads();
        {
            float d = g_dinv[il];
            sh[half][fl] = d * g_aggh[il * H1C + fl];
        }
        __syncthreads();
        float v0 = bias, v1 = bias;
#pragma unroll
        for (int k = 0; k < H1C; k++) {
            v0 = fmaf(sh[0][k], wcol[k], v0);
            v1 = fmaf(sh[1][k], wcol[k], v1);
        }
        float h20 = fmaxf(v0, 0.f);
        float h21 = fmaxf(v1, 0.f);

        int gA = batch[i0];
        if (gA != cur_g) {
            red_add_f(&g_pool[cur_g * H2C + tid], acc);
            if (tid == 0) red_add_f(&g_cnt[cur_g], cntacc);
            acc = 0.f; cntacc = 0.f; cur_g = gA;
        }
        acc += h20; cntacc += 1.f;

        int gB = batch[i0 + 1];
        if (gB != cur_g) {
            red_add_f(&g_pool[cur_g * H2C + tid], acc);
            if (tid == 0) red_add_f(&g_cnt[cur_g], cntacc);
            acc = 0.f; cntacc = 0.f; cur_g = gB;
        }
        acc += h21; cntacc += 1.f;
    }
    red_add_f(&g_pool[cur_g * H2C + tid], acc);
    if (tid == 0) red_add_f(&g_cnt[cur_g], cntacc);
}

// ---------------------------------------- final: out = (pool/cnt)@Wfc + bfc
__global__ void k_out(const float* __restrict__ Wfc, const float* __restrict__ bfc,
                      float* __restrict__ out) {
    int t = blockIdx.x * blockDim.x + threadIdx.x;
    if (t >= NG * OUTC) return;
    int g = t >> 1, o = t & 1;
    float inv = 1.0f / fmaxf(g_cnt[g], 1.0f);
    float s = 0.f;
#pragma unroll
    for (int k = 0; k < H2C; k++)
        s = fmaf(g_pool[g * H2C + k], __ldg(&Wfc[k * OUTC + o]), s);
    out[t] = s * inv + __ldg(&bfc[o]);
}

extern "C" void kernel_launch(void* const* d_in, const int* in_sizes, int n_in,
                              void* d_out, int out_size) {
    const float* x   = (const float*)d_in[0];
    const int*   ei  = (const int*)d_in[1];   // [2, E] int32
    const int*   bat = (const int*)d_in[2];   // [N] int32
    const float* W1  = (const float*)d_in[3];
    const float* b1  = (const float*)d_in[4];
    const float* W2  = (const float*)d_in[5];
    const float* b2  = (const float*)d_in[6];
    const float* Wfc = (const float*)d_in[7];
    const float* bfc = (const float*)d_in[8];
    float*       out = (float*)d_out;

    const int* src = ei;
    const int* dst = ei + NE;

    const int T = 256;
    k_zero<<<(NN / 4 + T - 1) / T, T>>>();
    k_deg <<<(NE + T - 1) / T, T>>>(dst);
    k_dinv<<<(NN + T - 1) / T, T>>>(x);
    k_ex  <<<(NE + T - 1) / T, T>>>(src, dst);
    k_l1  <<<(NN * H1C + T - 1) / T, T>>>(W1, b1);
    k_eh  <<<(int)(((long long)NE * 16 + T - 1) / T), T>>>(src, dst);
    k_l2  <<<(NN + NPB - 1) / NPB, 128>>>(W2, b2, bat);
    k_out <<<(NG * OUTC + T - 1) / T, T>>>(Wfc, bfc, out);
}

// round 6
// speedup vs baseline: 2.8009x; 1.1428x over previous
#include <cuda_runtime.h>
#include <cuda_bf16.h>

#define NN 100000
#define NE 1600000
#define NG 512
#define H1C 64
#define H2C 128
#define OUTC 2
#define NPB 32          // nodes per block in k_l2
#define NBS 98          // ceil(NN / 1024) scan blocks

// ---------------- scratch (__device__ globals) ----------------
__device__ __align__(16) int   g_icnt[NN];       // in-degree (edge count at dst)
__device__ __align__(16) int   g_off [NN];       // CSR exclusive offsets
__device__ __align__(16) int   g_cur [NN];       // scatter cursors
__device__ __align__(16) int   g_bsum[128];      // scan block sums
__device__ __align__(16) int   g_csrc[NE];       // CSR: src node per slot
__device__ __align__(16) float g_dinv[NN];
__device__ __align__(16) float g_xs4 [NN * 4];   // {d*x0, d*x1, d*x2, d}
__device__ __align__(16) float g_h1s [NN * H1C]; // dinv-scaled relu(layer1)
__device__ __align__(16) float g_agg [NN * H1C]; // layer-2 aggregated (pre-scaled)
__device__ __align__(16) float g_pool[NG * H2C];
__device__ __align__(16) float g_cnt [NG];

__device__ __forceinline__ void red_add_f(float* addr, float v) {
    asm volatile("red.global.add.f32 [%0], %1;" :: "l"(addr), "f"(v) : "memory");
}

// -------------------- zero: icnt, pool, cnt (grid must cover NN/4 = 25000!)
__global__ void k_zero() {
    int i = blockIdx.x * blockDim.x + threadIdx.x;
    if (i < NN / 4)       ((int4*)g_icnt)[i]   = make_int4(0, 0, 0, 0);
    if (i < NG * H2C / 4) ((float4*)g_pool)[i] = make_float4(0.f, 0.f, 0.f, 0.f);
    if (i < NG / 4)       ((float4*)g_cnt)[i]  = make_float4(0.f, 0.f, 0.f, 0.f);
}

// ---------------------------------------------- in-degree count
__global__ void k_count(const int* __restrict__ dst) {
    int e = blockIdx.x * blockDim.x + threadIdx.x;
    if (e < NE) atomicAdd(&g_icnt[dst[e]], 1);
}

// ---------------------------------------------- scan pass 1: per-1024 chunks
__global__ void __launch_bounds__(256) k_scan1() {
    __shared__ int sh[256];
    int base = blockIdx.x * 1024;
    int t = threadIdx.x;
    int v[4], s = 0;
#pragma unroll
    for (int j = 0; j < 4; j++) {
        int idx = base + t * 4 + j;
        v[j] = (idx < NN) ? g_icnt[idx] : 0;
        s += v[j];
    }
    sh[t] = s;
    __syncthreads();
    for (int o = 1; o < 256; o <<= 1) {
        int x = (t >= o) ? sh[t - o] : 0;
        __syncthreads();
        sh[t] += x;
        __syncthreads();
    }
    int run = sh[t] - s;  // exclusive prefix of this thread within chunk
#pragma unroll
    for (int j = 0; j < 4; j++) {
        int idx = base + t * 4 + j;
        if (idx < NN) g_off[idx] = run;
        run += v[j];
    }
    if (t == 255) g_bsum[blockIdx.x] = sh[255];
}

// ---------------------------------------------- scan pass 2: block sums (1 block)
__global__ void __launch_bounds__(128) k_scan2() {
    __shared__ int sh[128];
    int t = threadIdx.x;
    int v = (t < NBS) ? g_bsum[t] : 0;
    sh[t] = v;
    __syncthreads();
    for (int o = 1; o < 128; o <<= 1) {
        int x = (t >= o) ? sh[t - o] : 0;
        __syncthreads();
        sh[t] += x;
        __syncthreads();
    }
    if (t < NBS) g_bsum[t] = sh[t] - v;  // exclusive
}

// ---------------------------------------------- scan pass 3: add block offset
__global__ void k_scan3() {
    int i = blockIdx.x * blockDim.x + threadIdx.x;
    if (i < NN) {
        int o = g_off[i] + g_bsum[i >> 10];
        g_off[i] = o;
        g_cur[i] = o;
    }
}

// ---------------------------------------------- CSR fill
__global__ void k_fill(const int* __restrict__ src, const int* __restrict__ dst) {
    int e = blockIdx.x * blockDim.x + threadIdx.x;
    if (e >= NE) return;
    int d = dst[e];
    int pos = atomicAdd(&g_cur[d], 1);
    g_csrc[pos] = src[e];
}

// ---------------------------------------------- dinv + scaled features
__global__ void k_dinv(const float* __restrict__ x) {
    int i = blockIdx.x * blockDim.x + threadIdx.x;
    if (i >= NN) return;
    float d = rsqrtf((float)g_icnt[i] + 1.0f);
    g_dinv[i] = d;
    ((float4*)g_xs4)[i] =
        make_float4(d * x[i * 3 + 0], d * x[i * 3 + 1], d * x[i * 3 + 2], d);
}

// ------- layer 1 fused gather + dense (warp per node)
// a = d_i * (sum_{s in N(i)} xs[s] + xs[i]);  h1s = d_i * relu(a@W1 + b1)
__global__ void __launch_bounds__(128) k_l1g(const float* __restrict__ W1,
                                             const float* __restrict__ b1) {
    int warp = threadIdx.x >> 5;
    int lane = threadIdx.x & 31;
    int node = blockIdx.x * 4 + warp;
    if (node >= NN) return;

    int beg = g_off[node];
    int cnt = g_icnt[node];
    float sx = 0.f, sy = 0.f, sz = 0.f;
    for (int j = lane; j < cnt; j += 32) {
        int s = g_csrc[beg + j];
        float4 v = ((const float4*)g_xs4)[s];
        sx += v.x; sy += v.y; sz += v.z;
    }
#pragma unroll
    for (int o = 16; o; o >>= 1) {
        sx += __shfl_xor_sync(0xffffffffu, sx, o);
        sy += __shfl_xor_sync(0xffffffffu, sy, o);
        sz += __shfl_xor_sync(0xffffffffu, sz, o);
    }
    float4 self = ((const float4*)g_xs4)[node];
    float d = self.w;
    float a0 = d * (sx + self.x);
    float a1 = d * (sy + self.y);
    float a2 = d * (sz + self.z);

    float2 hv;
    {
        int f = lane * 2;
        float v0 = a0 * __ldg(&W1[f])     + a1 * __ldg(&W1[64 + f])
                 + a2 * __ldg(&W1[128 + f]) + __ldg(&b1[f]);
        float v1 = a0 * __ldg(&W1[f + 1])     + a1 * __ldg(&W1[64 + f + 1])
                 + a2 * __ldg(&W1[128 + f + 1]) + __ldg(&b1[f + 1]);
        hv.x = d * fmaxf(v0, 0.f);
        hv.y = d * fmaxf(v1, 0.f);
    }
    ((float2*)g_h1s)[node * 32 + lane] = hv;
}

// ------- layer 2 edge aggregation via CSR (warp per node, register acc)
// agg[i] = d_i * (sum_{s in N(i)} h1s[s] + h1s[i])
__global__ void __launch_bounds__(128) k_eh() {
    int warp = threadIdx.x >> 5;
    int lane = threadIdx.x & 31;
    int node = blockIdx.x * 4 + warp;
    if (node >= NN) return;

    int beg = g_off[node];
    int cnt = g_icnt[node];
    const float2* H = (const float2*)g_h1s;
    float2 acc = H[node * 32 + lane];   // self term
#pragma unroll 4
    for (int j = 0; j < cnt; j++) {
        int s = g_csrc[beg + j];
        float2 v = H[s * 32 + lane];
        acc.x += v.x;
        acc.y += v.y;
    }
    float d = g_dinv[node];
    acc.x *= d;
    acc.y *= d;
    ((float2*)g_agg)[node * 32 + lane] = acc;
}

// ---- layer-2 dense + fused mean-pool (batch sorted -> run-flush), 2 nodes/iter
__global__ void __launch_bounds__(128)
k_l2(const float* __restrict__ W2, const float* __restrict__ b2,
     const int* __restrict__ batch) {
    int tid = threadIdx.x;
    int half = tid >> 6;
    int fl = tid & 63;
    float wcol[H1C];
#pragma unroll
    for (int k = 0; k < H1C; k++) wcol[k] = __ldg(&W2[k * H2C + tid]);
    float bias = __ldg(&b2[tid]);

    __shared__ float sh[2][H1C];
    int node0 = blockIdx.x * NPB;
    if (node0 >= NN) return;

    float acc = 0.f, cntacc = 0.f;
    int cur_g = batch[node0];

    for (int n = 0; n < NPB; n += 2) {
        int i0 = node0 + n;
        int il = i0 + half;
        __syncthreads();
        sh[half][fl] = g_agg[il * H1C + fl];
        __syncthreads();
        float v0 = bias, v1 = bias;
#pragma unroll
        for (int k = 0; k < H1C; k++) {
            v0 = fmaf(sh[0][k], wcol[k], v0);
            v1 = fmaf(sh[1][k], wcol[k], v1);
        }
        float h20 = fmaxf(v0, 0.f);
        float h21 = fmaxf(v1, 0.f);

        int gA = batch[i0];
        if (gA != cur_g) {
            red_add_f(&g_pool[cur_g * H2C + tid], acc);
            if (tid == 0) red_add_f(&g_cnt[cur_g], cntacc);
            acc = 0.f; cntacc = 0.f; cur_g = gA;
        }
        acc += h20; cntacc += 1.f;

        int gB = batch[i0 + 1];
        if (gB != cur_g) {
            red_add_f(&g_pool[cur_g * H2C + tid], acc);
            if (tid == 0) red_add_f(&g_cnt[cur_g], cntacc);
            acc = 0.f; cntacc = 0.f; cur_g = gB;
        }
        acc += h21; cntacc += 1.f;
    }
    red_add_f(&g_pool[cur_g * H2C + tid], acc);
    if (tid == 0) red_add_f(&g_cnt[cur_g], cntacc);
}

// ---------------------------------------- final: out = (pool/cnt)@Wfc + bfc
__global__ void k_out(const float* __restrict__ Wfc, const float* __restrict__ bfc,
                      float* __restrict__ out) {
    int t = blockIdx.x * blockDim.x + threadIdx.x;
    if (t >= NG * OUTC) return;
    int g = t >> 1, o = t & 1;
    float inv = 1.0f / fmaxf(g_cnt[g], 1.0f);
    float s = 0.f;
#pragma unroll
    for (int k = 0; k < H2C; k++)
        s = fmaf(g_pool[g * H2C + k], __ldg(&Wfc[k * OUTC + o]), s);
    out[t] = s * inv + __ldg(&bfc[o]);
}

extern "C" void kernel_launch(void* const* d_in, const int* in_sizes, int n_in,
                              void* d_out, int out_size) {
    const float* x   = (const float*)d_in[0];
    const int*   ei  = (const int*)d_in[1];   // [2, E] int32
    const int*   bat = (const int*)d_in[2];   // [N] int32
    const float* W1  = (const float*)d_in[3];
    const float* b1  = (const float*)d_in[4];
    const float* W2  = (const float*)d_in[5];
    const float* b2  = (const float*)d_in[6];
    const float* Wfc = (const float*)d_in[7];
    const float* bfc = (const float*)d_in[8];
    float*       out = (float*)d_out;

    const int* src = ei;
    const int* dst = ei + NE;

    const int T = 256;
    k_zero <<<(NN / 4 + T - 1) / T, T>>>();   // FIX: cover NN/4 (idempotent zeroing)
    k_count<<<(NE + T - 1) / T, T>>>(dst);
    k_scan1<<<NBS, 256>>>();
    k_scan2<<<1, 128>>>();
    k_scan3<<<(NN + T - 1) / T, T>>>();
    k_fill <<<(NE + T - 1) / T, T>>>(src, dst);
    k_dinv <<<(NN + T - 1) / T, T>>>(x);
    k_l1g  <<<NN / 4, 128>>>(W1, b1);
    k_eh   <<<NN / 4, 128>>>();
    k_l2   <<<(NN + NPB - 1) / NPB, 128>>>(W2, b2, bat);
    k_out  <<<(NG * OUTC + T - 1) / T, T>>>(Wfc, bfc, out);
}

// round 7
// speedup vs baseline: 2.8757x; 1.0267x over previous
#include <cuda_runtime.h>
#include <cuda_fp16.h>
#include <cuda_bf16.h>

#define NN 100000
#define NE 1600000
#define NG 512
#define H1C 64
#define H2C 128
#define OUTC 2
#define NPB 32          // nodes per block in k_l2
#define NBS 98          // ceil(NN / 1024) scan blocks

// ---------------- scratch (__device__ globals) ----------------
__device__ __align__(16) int     g_icnt[NN];        // in-degree (edge count at dst)
__device__ __align__(16) int     g_off [NN];        // CSR exclusive offsets
__device__ __align__(16) int     g_cur [NN];        // scatter cursors
__device__ __align__(16) int     g_bsum[128];       // scan block sums
__device__ __align__(16) int     g_csrc[NE];        // CSR: src node per slot
__device__ __align__(16) float   g_dinv[NN];
__device__ __align__(16) float   g_xs4 [NN * 4];    // {d*x0, d*x1, d*x2, d}
__device__ __align__(16) __half2 g_h1h [NN * 32];   // fp16 dinv-scaled relu(layer1): 64 feats
__device__ __align__(16) float   g_agg [NN * H1C];  // layer-2 aggregated (fp32, pre-scaled)
__device__ __align__(16) float   g_pool[NG * H2C];
__device__ __align__(16) float   g_cnt [NG];

__device__ __forceinline__ void red_add_f(float* addr, float v) {
    asm volatile("red.global.add.f32 [%0], %1;" :: "l"(addr), "f"(v) : "memory");
}

// -------------------- zero: icnt, pool, cnt (grid covers NN/4 = 25000)
__global__ void k_zero() {
    int i = blockIdx.x * blockDim.x + threadIdx.x;
    if (i < NN / 4)       ((int4*)g_icnt)[i]   = make_int4(0, 0, 0, 0);
    if (i < NG * H2C / 4) ((float4*)g_pool)[i] = make_float4(0.f, 0.f, 0.f, 0.f);
    if (i < NG / 4)       ((float4*)g_cnt)[i]  = make_float4(0.f, 0.f, 0.f, 0.f);
}

// ---------------------------------------------- in-degree count
__global__ void k_count(const int* __restrict__ dst) {
    int e = blockIdx.x * blockDim.x + threadIdx.x;
    if (e < NE) atomicAdd(&g_icnt[dst[e]], 1);
}

// ---------------------------------------------- scan pass 1: per-1024 chunks
__global__ void __launch_bounds__(256) k_scan1() {
    __shared__ int sh[256];
    int base = blockIdx.x * 1024;
    int t = threadIdx.x;
    int v[4], s = 0;
#pragma unroll
    for (int j = 0; j < 4; j++) {
        int idx = base + t * 4 + j;
        v[j] = (idx < NN) ? g_icnt[idx] : 0;
        s += v[j];
    }
    sh[t] = s;
    __syncthreads();
    for (int o = 1; o < 256; o <<= 1) {
        int x = (t >= o) ? sh[t - o] : 0;
        __syncthreads();
        sh[t] += x;
        __syncthreads();
    }
    int run = sh[t] - s;
#pragma unroll
    for (int j = 0; j < 4; j++) {
        int idx = base + t * 4 + j;
        if (idx < NN) g_off[idx] = run;
        run += v[j];
    }
    if (t == 255) g_bsum[blockIdx.x] = sh[255];
}

// ---------------------------------------------- scan pass 2: block sums (1 block)
__global__ void __launch_bounds__(128) k_scan2() {
    __shared__ int sh[128];
    int t = threadIdx.x;
    int v = (t < NBS) ? g_bsum[t] : 0;
    sh[t] = v;
    __syncthreads();
    for (int o = 1; o < 128; o <<= 1) {
        int x = (t >= o) ? sh[t - o] : 0;
        __syncthreads();
        sh[t] += x;
        __syncthreads();
    }
    if (t < NBS) g_bsum[t] = sh[t] - v;
}

// -------------------- scan pass 3 + dinv + scaled features (merged per-node)
__global__ void k_scan3(const float* __restrict__ x) {
    int i = blockIdx.x * blockDim.x + threadIdx.x;
    if (i >= NN) return;
    int o = g_off[i] + g_bsum[i >> 10];
    g_off[i] = o;
    g_cur[i] = o;
    float d = rsqrtf((float)g_icnt[i] + 1.0f);
    g_dinv[i] = d;
    ((float4*)g_xs4)[i] =
        make_float4(d * x[i * 3 + 0], d * x[i * 3 + 1], d * x[i * 3 + 2], d);
}

// ---------------------------------------------- CSR fill
__global__ void k_fill(const int* __restrict__ src, const int* __restrict__ dst) {
    int e = blockIdx.x * blockDim.x + threadIdx.x;
    if (e >= NE) return;
    int d = dst[e];
    int pos = atomicAdd(&g_cur[d], 1);
    g_csrc[pos] = src[e];
}

// ------- layer 1 fused gather + dense (warp per node), fp16 output
__global__ void __launch_bounds__(128) k_l1g(const float* __restrict__ W1,
                                             const float* __restrict__ b1) {
    int warp = threadIdx.x >> 5;
    int lane = threadIdx.x & 31;
    int node = blockIdx.x * 4 + warp;
    if (node >= NN) return;

    int beg = g_off[node];
    int cnt = g_icnt[node];
    float sx = 0.f, sy = 0.f, sz = 0.f;
    for (int j = lane; j < cnt; j += 32) {
        int s = g_csrc[beg + j];
        float4 v = ((const float4*)g_xs4)[s];
        sx += v.x; sy += v.y; sz += v.z;
    }
#pragma unroll
    for (int o = 16; o; o >>= 1) {
        sx += __shfl_xor_sync(0xffffffffu, sx, o);
        sy += __shfl_xor_sync(0xffffffffu, sy, o);
        sz += __shfl_xor_sync(0xffffffffu, sz, o);
    }
    float4 self = ((const float4*)g_xs4)[node];
    float d = self.w;
    float a0 = d * (sx + self.x);
    float a1 = d * (sy + self.y);
    float a2 = d * (sz + self.z);

    int f = lane * 2;
    float v0 = a0 * __ldg(&W1[f])       + a1 * __ldg(&W1[64 + f])
             + a2 * __ldg(&W1[128 + f])   + __ldg(&b1[f]);
    float v1 = a0 * __ldg(&W1[f + 1])   + a1 * __ldg(&W1[64 + f + 1])
             + a2 * __ldg(&W1[128 + f + 1]) + __ldg(&b1[f + 1]);
    g_h1h[node * 32 + lane] =
        __floats2half2_rn(d * fmaxf(v0, 0.f), d * fmaxf(v1, 0.f));
}

// ------- layer 2 edge aggregation via CSR (warp per node, fp32 register acc)
// agg[i] = d_i * (sum_{s in N(i)} h1s[s] + h1s[i]);  h1s stored fp16
__global__ void __launch_bounds__(128) k_eh() {
    int warp = threadIdx.x >> 5;
    int lane = threadIdx.x & 31;
    int node = blockIdx.x * 4 + warp;
    if (node >= NN) return;

    int beg = g_off[node];
    int cnt = g_icnt[node];
    const __half2* H = g_h1h;

    float2 accA = __half22float2(H[node * 32 + lane]);  // self term
    float2 accB = make_float2(0.f, 0.f);

    int j = 0;
#pragma unroll 2
    for (; j + 2 <= cnt; j += 2) {
        int s0 = g_csrc[beg + j];
        int s1 = g_csrc[beg + j + 1];
        float2 v0 = __half22float2(H[s0 * 32 + lane]);
        float2 v1 = __half22float2(H[s1 * 32 + lane]);
        accA.x += v0.x; accA.y += v0.y;
        accB.x += v1.x; accB.y += v1.y;
    }
    if (j < cnt) {
        int s = g_csrc[beg + j];
        float2 v = __half22float2(H[s * 32 + lane]);
        accA.x += v.x; accA.y += v.y;
    }
    float d = g_dinv[node];
    float2 outv = make_float2(d * (accA.x + accB.x), d * (accA.y + accB.y));
    ((float2*)g_agg)[node * 32 + lane] = outv;
}

// ---- layer-2 dense + fused mean-pool (batch sorted -> run-flush), 2 nodes/iter
__global__ void __launch_bounds__(128)
k_l2(const float* __restrict__ W2, const float* __restrict__ b2,
     const int* __restrict__ batch) {
    int tid = threadIdx.x;
    int half = tid >> 6;
    int fl = tid & 63;
    float wcol[H1C];
#pragma unroll
    for (int k = 0; k < H1C; k++) wcol[k] = __ldg(&W2[k * H2C + tid]);
    float bias = __ldg(&b2[tid]);

    __shared__ float sh[2][H1C];
    int node0 = blockIdx.x * NPB;
    if (node0 >= NN) return;

    float acc = 0.f, cntacc = 0.f;
    int cur_g = batch[node0];

    for (int n = 0; n < NPB; n += 2) {
        int i0 = node0 + n;
        int il = i0 + half;
        __syncthreads();
        sh[half][fl] = g_agg[il * H1C + fl];
        __syncthreads();
        float v0 = bias, v1 = bias;
#pragma unroll
        for (int k = 0; k < H1C; k++) {
            v0 = fmaf(sh[0][k], wcol[k], v0);
            v1 = fmaf(sh[1][k], wcol[k], v1);
        }
        float h20 = fmaxf(v0, 0.f);
        float h21 = fmaxf(v1, 0.f);

        int gA = batch[i0];
        if (gA != cur_g) {
            red_add_f(&g_pool[cur_g * H2C + tid], acc);
            if (tid == 0) red_add_f(&g_cnt[cur_g], cntacc);
            acc = 0.f; cntacc = 0.f; cur_g = gA;
        }
        acc += h20; cntacc += 1.f;

        int gB = batch[i0 + 1];
        if (gB != cur_g) {
            red_add_f(&g_pool[cur_g * H2C + tid], acc);
            if (tid == 0) red_add_f(&g_cnt[cur_g], cntacc);
            acc = 0.f; cntacc = 0.f; cur_g = gB;
        }
        acc += h21; cntacc += 1.f;
    }
    red_add_f(&g_pool[cur_g * H2C + tid], acc);
    if (tid == 0) red_add_f(&g_cnt[cur_g], cntacc);
}

// ---------------------------------------- final: out = (pool/cnt)@Wfc + bfc
__global__ void k_out(const float* __restrict__ Wfc, const float* __restrict__ bfc,
                      float* __restrict__ out) {
    int t = blockIdx.x * blockDim.x + threadIdx.x;
    if (t >= NG * OUTC) return;
    int g = t >> 1, o = t & 1;
    float inv = 1.0f / fmaxf(g_cnt[g], 1.0f);
    float s = 0.f;
#pragma unroll
    for (int k = 0; k < H2C; k++)
        s = fmaf(g_pool[g * H2C + k], __ldg(&Wfc[k * OUTC + o]), s);
    out[t] = s * inv + __ldg(&bfc[o]);
}

extern "C" void kernel_launch(void* const* d_in, const int* in_sizes, int n_in,
                              void* d_out, int out_size) {
    const float* x   = (const float*)d_in[0];
    const int*   ei  = (const int*)d_in[1];   // [2, E] int32
    const int*   bat = (const int*)d_in[2];   // [N] int32
    const float* W1  = (const float*)d_in[3];
    const float* b1  = (const float*)d_in[4];
    const float* W2  = (const float*)d_in[5];
    const float* b2  = (const float*)d_in[6];
    const float* Wfc = (const float*)d_in[7];
    const float* bfc = (const float*)d_in[8];
    float*       out = (float*)d_out;

    const int* src = ei;
    const int* dst = ei + NE;

    const int T = 256;
    k_zero <<<(NN / 4 + T - 1) / T, T>>>();
    k_count<<<(NE + T - 1) / T, T>>>(dst);
    k_scan1<<<NBS, 256>>>();
    k_scan2<<<1, 128>>>();
    k_scan3<<<(NN + T - 1) / T, T>>>(x);   // merged: offsets + cursors + dinv + xs4
    k_fill <<<(NE + T - 1) / T, T>>>(src, dst);
    k_l1g  <<<NN / 4, 128>>>(W1, b1);
    k_eh   <<<NN / 4, 128>>>();
    k_l2   <<<(NN + NPB - 1) / NPB, 128>>>(W2, b2, bat);
    k_out  <<<(NG * OUTC + T - 1) / T, T>>>(Wfc, bfc, out);
}